// round 14
// baseline (speedup 1.0000x reference)
#include <cuda_runtime.h>
#include <cuda_bf16.h>
#include <cstdint>
#include <cstddef>
#include <math.h>

#define T_TOK 4096
#define H_DIM 2048
#define I_DIM 2048
#define N_EXP 16
#define TOPK  2
#define NROWS (T_TOK * TOPK)
#define HPAD  128
#define MAXTILE 80

#define BK32   32
#define KT32   (H_DIM / BK32)     // 64
#define TILE_SZ 16384u            // 128 rows x 128B (hi|lo interleaved)
#define STAGE_SZ 32768u           // A tile + B tile
#define SMEM_DYN (3 * STAGE_SZ + 128)

// ---------------- routing scratch -------------------------------------------
__device__ int   g_offset[N_EXP + 1];
__device__ int   g_tids[NROWS];
__device__ float g_tw[NROWS];
__device__ int   g_tok[NROWS + HPAD];
__device__ float g_cf[NROWS + HPAD];
__device__ int   g_slot[NROWS + HPAD];
__device__ int   g_tile_e[MAXTILE];
__device__ int   g_tile_m0[MAXTILE];
__device__ int   g_ntile;

// ---------------- bf16 hi/lo split operand storage --------------------------
__device__ __nv_bfloat16 xb_hi[(size_t)T_TOK * H_DIM];
__device__ __nv_bfloat16 xb_lo[(size_t)T_TOK * H_DIM];
__device__ __nv_bfloat16 wsb_hi[(size_t)N_EXP * 2 * I_DIM * H_DIM];
__device__ __nv_bfloat16 wsb_lo[(size_t)N_EXP * 2 * I_DIM * H_DIM];
__device__ __nv_bfloat16 w2b_hi[(size_t)N_EXP * H_DIM * I_DIM];
__device__ __nv_bfloat16 w2b_lo[(size_t)N_EXP * H_DIM * I_DIM];
__device__ __nv_bfloat16 hb_hi[(size_t)(NROWS + HPAD) * I_DIM];
__device__ __nv_bfloat16 hb_lo[(size_t)(NROWS + HPAD) * I_DIM];
__device__ float g_y[TOPK][(size_t)T_TOK * H_DIM];

// ---------------- helpers ----------------------------------------------------
__device__ __forceinline__ uint32_t smem_u32(const void* p) {
    uint32_t r;
    asm("{ .reg .u64 t; cvta.to.shared.u64 t, %1; cvt.u32.u64 %0, t; }"
        : "=r"(r) : "l"(p));
    return r;
}
__device__ __forceinline__ void ldm4(uint32_t a, uint32_t& r0, uint32_t& r1,
                                     uint32_t& r2, uint32_t& r3) {
    asm volatile("ldmatrix.sync.aligned.m8n8.x4.shared.b16 {%0,%1,%2,%3}, [%4];"
                 : "=r"(r0), "=r"(r1), "=r"(r2), "=r"(r3) : "r"(a));
}
__device__ __forceinline__ void mma_bf16(float* d, const uint32_t* a,
                                         uint32_t b0, uint32_t b1) {
    asm volatile(
        "mma.sync.aligned.m16n8k16.row.col.f32.bf16.bf16.f32 "
        "{%0,%1,%2,%3}, {%4,%5,%6,%7}, {%8,%9}, {%0,%1,%2,%3};"
        : "+f"(d[0]), "+f"(d[1]), "+f"(d[2]), "+f"(d[3])
        : "r"(a[0]), "r"(a[1]), "r"(a[2]), "r"(a[3]), "r"(b0), "r"(b1));
}
__device__ __forceinline__ uint32_t pack_bf16(__nv_bfloat16 a, __nv_bfloat16 b) {
    return (uint32_t)__bfloat16_as_ushort(a) |
           ((uint32_t)__bfloat16_as_ushort(b) << 16);
}
__device__ __forceinline__ void cp16(uint32_t dst, const void* src) {
    asm volatile("cp.async.cg.shared.global [%0], [%1], 16;" :: "r"(dst), "l"(src) : "memory");
}
#define CP_COMMIT() asm volatile("cp.async.commit_group;" ::: "memory")
#define CP_WAIT1()  asm volatile("cp.async.wait_group 1;" ::: "memory")
#define CP_WAIT0()  asm volatile("cp.async.wait_group 0;" ::: "memory")

// swizzled in-tile byte offset for (row, chunk16B) — store path
__device__ __forceinline__ uint32_t tof(int row, int ch) {
    return (uint32_t)(row * 128 + ((ch ^ (row & 7)) * 16));
}

// ---------------- gating: tiled 16 tokens x 16 experts -----------------------
__global__ __launch_bounds__(256) void gate_kernel(const float* __restrict__ x,
                                                   const float* __restrict__ gw) {
    __shared__ __align__(16) float xs[16][132];
    __shared__ __align__(16) float gs[16][132];
    __shared__ float lg[16][17];

    int tid = threadIdx.x;
    int t0  = blockIdx.x * 16;
    int tok = tid >> 4;
    int e   = tid & 15;
    float acc = 0.f;

    for (int kc = 0; kc < H_DIM; kc += 128) {
        __syncthreads();
        for (int i = tid; i < 512; i += 256) {
            int r = i >> 5, c4 = i & 31;
            *(float4*)&xs[r][c4 * 4] =
                *(const float4*)(x + (size_t)(t0 + r) * H_DIM + kc + c4 * 4);
            *(float4*)&gs[r][c4 * 4] =
                *(const float4*)(gw + (size_t)r * H_DIM + kc + c4 * 4);
        }
        __syncthreads();
#pragma unroll 16
        for (int k = 0; k < 128; k++) acc += xs[tok][k] * gs[e][k];
    }
    lg[tok][e] = acc;
    __syncthreads();

    if (tid < 16) {
        int t = t0 + tid;
        int b0 = 0; float v0 = lg[tid][0];
        for (int j = 1; j < N_EXP; j++)
            if (lg[tid][j] > v0) { v0 = lg[tid][j]; b0 = j; }
        int b1 = -1; float v1 = -3.4e38f;
        for (int j = 0; j < N_EXP; j++) {
            if (j == b0) continue;
            if (lg[tid][j] > v1) { v1 = lg[tid][j]; b1 = j; }
        }
        float w0 = 1.0f / (1.0f + expf(v1 - v0));
        g_tids[2 * t] = b0;   g_tids[2 * t + 1] = b1;
        g_tw[2 * t] = w0;     g_tw[2 * t + 1] = 1.0f - w0;
    }
}

// ---------------- fused fp32 -> bf16 hi/lo split of x, ws, w2s ---------------
__global__ __launch_bounds__(256) void cvt_all(const float* __restrict__ x,
                                               const float* __restrict__ ws,
                                               const float* __restrict__ w2s) {
    const size_t X4  = (size_t)T_TOK * H_DIM / 4;
    const size_t WS4 = (size_t)N_EXP * 2 * I_DIM * H_DIM / 4;
    const size_t W24 = (size_t)N_EXP * H_DIM * I_DIM / 4;
    const size_t TOT = X4 + WS4 + W24;
    size_t i = (size_t)blockIdx.x * blockDim.x + threadIdx.x;
    size_t stride = (size_t)gridDim.x * blockDim.x;
    for (; i < TOT; i += stride) {
        const float4* s4;
        uint2 *h2, *l2;
        size_t j;
        if (i < X4) {
            j = i; s4 = (const float4*)x;
            h2 = (uint2*)xb_hi; l2 = (uint2*)xb_lo;
        } else if (i < X4 + WS4) {
            j = i - X4; s4 = (const float4*)ws;
            h2 = (uint2*)wsb_hi; l2 = (uint2*)wsb_lo;
        } else {
            j = i - X4 - WS4; s4 = (const float4*)w2s;
            h2 = (uint2*)w2b_hi; l2 = (uint2*)w2b_lo;
        }
        float4 v = s4[j];
        __nv_bfloat16 h0 = __float2bfloat16_rn(v.x), h1 = __float2bfloat16_rn(v.y);
        __nv_bfloat16 hb = __float2bfloat16_rn(v.z), h3 = __float2bfloat16_rn(v.w);
        float l0 = v.x - __bfloat162float(h0), l1 = v.y - __bfloat162float(h1);
        float l2f = v.z - __bfloat162float(hb), l3 = v.w - __bfloat162float(h3);
        uint2 ph; ph.x = pack_bf16(h0, h1); ph.y = pack_bf16(hb, h3);
        uint2 pl;
        pl.x = pack_bf16(__float2bfloat16_rn(l0), __float2bfloat16_rn(l1));
        pl.y = pack_bf16(__float2bfloat16_rn(l2f), __float2bfloat16_rn(l3));
        h2[j] = ph;
        l2[j] = pl;
    }
}

// ---------------- single-block: count + prefix + scatter + tile list ---------
__global__ __launch_bounds__(256) void scan_scatter() {
    __shared__ int scnt[N_EXP];
    __shared__ int scur[N_EXP];
    __shared__ int soff[N_EXP];
    int tid = threadIdx.x;
    if (tid < N_EXP) { scnt[tid] = 0; scur[tid] = 0; }
    __syncthreads();
    for (int i = tid; i < NROWS; i += 256) atomicAdd(&scnt[g_tids[i]], 1);
    __syncthreads();
    if (tid == 0) {
        int s = 0, nt = 0;
        for (int e = 0; e < N_EXP; e++) {
            soff[e] = s; g_offset[e] = s;
            for (int m0 = 0; m0 < scnt[e]; m0 += 128) {
                g_tile_e[nt] = e; g_tile_m0[nt] = m0; nt++;
            }
            s += scnt[e];
        }
        g_offset[N_EXP] = s;
        g_ntile = nt;
    }
    __syncthreads();
    for (int t = tid; t < T_TOK; t += 256) {
#pragma unroll
        for (int k = 0; k < TOPK; k++) {
            int e = g_tids[2 * t + k];
            int pos = atomicAdd(&scur[e], 1);
            int r = soff[e] + pos;
            g_tok[r] = t; g_cf[r] = g_tw[2 * t + k]; g_slot[r] = k;
        }
    }
}

__global__ void combine_kernel(float* __restrict__ out) {
    size_t i = (size_t)blockIdx.x * blockDim.x + threadIdx.x;
    size_t n = (size_t)T_TOK * H_DIM / 4;
    size_t stride = (size_t)gridDim.x * blockDim.x;
    const float4* y0 = (const float4*)g_y[0];
    const float4* y1 = (const float4*)g_y[1];
    float4* o = (float4*)out;
    for (; i < n; i += stride) {
        float4 a = y0[i], b = y1[i];
        o[i] = make_float4(a.x + b.x, a.y + b.y, a.z + b.z, a.w + b.w);
    }
}

// ---------------- GEMM1: h = silu(x@Wg^T)*(x@Wu^T) ---------------------------
__global__ __launch_bounds__(256, 2) void gemm1_mma() {
    const int ts = blockIdx.y;
    if (ts >= g_ntile) return;
    const int e    = g_tile_e[ts];
    const int m0   = g_tile_m0[ts];
    const int base = g_offset[e];
    const int cnt  = g_offset[e + 1] - base;
    const int n0g  = blockIdx.x * 64;

    extern __shared__ __align__(128) char smem[];
    __shared__ int s_tok[128];
    const uint32_t sb = (smem_u32(smem) + 127u) & ~127u;

    const int tid = threadIdx.x;
    const int wid = tid >> 5, lane = tid & 31;
    const int warp_m = wid >> 2, warp_n = wid & 3;

    if (tid < 128) s_tok[tid] = (m0 + tid < cnt) ? g_tok[base + m0 + tid] : g_tok[base];
    __syncthreads();

    // ---- loader geometry: 4 rows/tile/thread, fixed 16B chunk --------------
    const int rbase = tid >> 3;          // 0..31
    const int ch    = tid & 7;           // <4 hi, >=4 lo
    const int kch   = ch & 3;
    const bool isLo = ch >= 4;
    const char* Ab = (const char*)(isLo ? xb_lo : xb_hi);
    const char* Bb = (const char*)(isLo ? wsb_lo : wsb_hi);
    uint32_t aoff[4], boff[4], dA[4], dB[4];
#pragma unroll
    for (int j = 0; j < 4; j++) {
        int row = rbase + j * 32;
        aoff[j] = ((uint32_t)s_tok[row] * H_DIM + kch * 8) * 2u;
        int brow = (row < 64) ? (n0g + row) : (I_DIM + n0g + row - 64);
        boff[j] = ((uint32_t)(e * 2 * I_DIM + brow) * H_DIM + kch * 8) * 2u;
        uint32_t off = tof(row, ch);
        dA[j] = sb + off;
        dB[j] = sb + TILE_SZ + off;
    }

    // ---- ldsm address bases (XOR-folded swizzle) ---------------------------
    const int lrow = lane & 15;
    const uint32_t X = (uint32_t)(lane >> 4) * 16u;
    uint32_t PB[2], PA[4];
#pragma unroll
    for (int p = 0; p < 2; p++) {
        int r = warp_n * 32 + p * 16 + lrow;
        PB[p] = (sb + TILE_SZ + (uint32_t)r * 128u + (uint32_t)(r & 7) * 16u) ^ X;
    }
#pragma unroll
    for (int mf = 0; mf < 4; mf++) {
        int r = warp_m * 64 + mf * 16 + lrow;
        PA[mf] = (sb + (uint32_t)r * 128u + (uint32_t)(r & 7) * 16u) ^ X;
    }

    float acc[4][4][4];
#pragma unroll
    for (int i = 0; i < 4; i++)
#pragma unroll
        for (int j = 0; j < 4; j++)
#pragma unroll
            for (int k = 0; k < 4; k++) acc[i][j][k] = 0.f;

    auto load_stage = [&](uint32_t soff, int kt) {
        uint32_t kb = (uint32_t)kt * 64u;
#pragma unroll
        for (int j = 0; j < 4; j++) {
            cp16(dA[j] + soff, Ab + aoff[j] + kb);
            cp16(dB[j] + soff, Bb + boff[j] + kb);
        }
        CP_COMMIT();
    };

    auto compute_stage = [&](uint32_t soff) {
#pragma unroll
        for (int s = 0; s < 2; s++) {
            uint32_t bh[2][4], bl[2][4];
#pragma unroll
            for (int p = 0; p < 2; p++) {
                uint32_t pb = PB[p] + soff;
                ldm4(pb ^ (uint32_t)(s * 32), bh[p][0], bh[p][1], bh[p][2], bh[p][3]);
                ldm4(pb ^ (uint32_t)(s * 32 + 64), bl[p][0], bl[p][1], bl[p][2], bl[p][3]);
            }
#pragma unroll
            for (int mf = 0; mf < 4; mf++) {
                uint32_t pa = PA[mf] + soff;
                uint32_t ah[4], al[4];
                ldm4(pa ^ (uint32_t)(s * 32), ah[0], ah[1], ah[2], ah[3]);
                ldm4(pa ^ (uint32_t)(s * 32 + 64), al[0], al[1], al[2], al[3]);
#pragma unroll
                for (int nf = 0; nf < 4; nf++) {
                    const int p = nf >> 1, q = nf & 1;
                    mma_bf16(acc[mf][nf], ah, bh[p][q], bh[p][q + 2]);
                }
#pragma unroll
                for (int nf = 0; nf < 4; nf++) {
                    const int p = nf >> 1, q = nf & 1;
                    mma_bf16(acc[mf][nf], ah, bl[p][q], bl[p][q + 2]);
                }
#pragma unroll
                for (int nf = 0; nf < 4; nf++) {
                    const int p = nf >> 1, q = nf & 1;
                    mma_bf16(acc[mf][nf], al, bh[p][q], bh[p][q + 2]);
                }
            }
        }
    };

    load_stage(0u, 0);
    load_stage(STAGE_SZ, 1);

#pragma unroll 1
    for (int kt = 0; kt < KT32 - 1; kt += 3) {
        CP_WAIT1(); __syncthreads();
        if (kt + 2 < KT32) load_stage(2u * STAGE_SZ, kt + 2);
        compute_stage(0u);
        CP_WAIT1(); __syncthreads();
        if (kt + 3 < KT32) load_stage(0u, kt + 3);
        compute_stage(STAGE_SZ);
        CP_WAIT1(); __syncthreads();
        if (kt + 4 < KT32) load_stage(STAGE_SZ, kt + 4);
        compute_stage(2u * STAGE_SZ);
    }
    CP_WAIT0(); __syncthreads();
    compute_stage(0u);     // kt = 63, slot 0

    // ---- epilogue: exchange gate via smem, fused SiLU, write bf16 h --------
    __syncthreads();
    float* sg = (float*)smem;            // [128][68]
    const int qr = lane >> 2, qc = (lane & 3) * 2;
    if (warp_n < 2) {
#pragma unroll
        for (int mf = 0; mf < 4; mf++)
#pragma unroll
            for (int nf = 0; nf < 4; nf++) {
                int r = warp_m * 64 + mf * 16 + qr;
                int c = warp_n * 32 + nf * 8 + qc;
                sg[r * 68 + c]           = acc[mf][nf][0];
                sg[r * 68 + c + 1]       = acc[mf][nf][1];
                sg[(r + 8) * 68 + c]     = acc[mf][nf][2];
                sg[(r + 8) * 68 + c + 1] = acc[mf][nf][3];
            }
    }
    __syncthreads();
    if (warp_n >= 2) {
#pragma unroll
        for (int mf = 0; mf < 4; mf++)
#pragma unroll
            for (int nf = 0; nf < 4; nf++) {
                int r = warp_m * 64 + mf * 16 + qr;
                int cu = (warp_n - 2) * 32 + nf * 8 + qc;
#pragma unroll
                for (int rr = 0; rr < 2; rr++) {
                    int rloc = r + rr * 8;
                    if (m0 + rloc < cnt) {
                        float g0 = sg[rloc * 68 + cu];
                        float g1 = sg[rloc * 68 + cu + 1];
                        float u0 = acc[mf][nf][rr * 2];
                        float u1 = acc[mf][nf][rr * 2 + 1];
                        float h0 = g0 / (1.0f + expf(-g0)) * u0;
                        float h1 = g1 / (1.0f + expf(-g1)) * u1;
                        size_t idx = (size_t)(base + m0 + rloc) * I_DIM + n0g + cu;
                        __nv_bfloat16 b0 = __float2bfloat16_rn(h0);
                        __nv_bfloat16 b1 = __float2bfloat16_rn(h1);
                        float l0 = h0 - __bfloat162float(b0);
                        float l1 = h1 - __bfloat162float(b1);
                        *(uint32_t*)(hb_hi + idx) = pack_bf16(b0, b1);
                        *(uint32_t*)(hb_lo + idx) =
                            pack_bf16(__float2bfloat16_rn(l0), __float2bfloat16_rn(l1));
                    }
                }
            }
    }
}

// ---------------- GEMM2: y[slot] = coef * (h @ W2^T) -------------------------
__global__ __launch_bounds__(256, 2) void gemm2_mma() {
    const int ts = blockIdx.y;
    if (ts >= g_ntile) return;
    const int e    = g_tile_e[ts];
    const int m0   = g_tile_m0[ts];
    const int base = g_offset[e];
    const int cnt  = g_offset[e + 1] - base;
    const int n0   = blockIdx.x * 128;

    extern __shared__ __align__(128) char smem[];
    const uint32_t sb = (smem_u32(smem) + 127u) & ~127u;

    const int tid = threadIdx.x;
    const int wid = tid >> 5, lane = tid & 31;
    const int warp_m = wid >> 2, warp_n = wid & 3;

    const int rbase = tid >> 3;
    const int ch    = tid & 7;
    const int kch   = ch & 3;
    const bool isLo = ch >= 4;
    const char* Ab = (const char*)(isLo ? hb_lo : hb_hi);
    const char* Bb = (const char*)(isLo ? w2b_lo : w2b_hi);
    uint32_t aoff[4], boff[4], dA[4], dB[4];
#pragma unroll
    for (int j = 0; j < 4; j++) {
        int row = rbase + j * 32;
        int ridx = (m0 + row < cnt) ? (base + m0 + row) : base;
        aoff[j] = ((uint32_t)ridx * I_DIM + kch * 8) * 2u;
        boff[j] = ((uint32_t)(e * H_DIM + n0 + row) * I_DIM + kch * 8) * 2u;
        uint32_t off = tof(row, ch);
        dA[j] = sb + off;
        dB[j] = sb + TILE_SZ + off;
    }

    const int lrow = lane & 15;
    const uint32_t X = (uint32_t)(lane >> 4) * 16u;
    uint32_t PB[2], PA[4];
#pragma unroll
    for (int p = 0; p < 2; p++) {
        int r = warp_n * 32 + p * 16 + lrow;
        PB[p] = (sb + TILE_SZ + (uint32_t)r * 128u + (uint32_t)(r & 7) * 16u) ^ X;
    }
#pragma unroll
    for (int mf = 0; mf < 4; mf++) {
        int r = warp_m * 64 + mf * 16 + lrow;
        PA[mf] = (sb + (uint32_t)r * 128u + (uint32_t)(r & 7) * 16u) ^ X;
    }

    float acc[4][4][4];
#pragma unroll
    for (int i = 0; i < 4; i++)
#pragma unroll
        for (int j = 0; j < 4; j++)
#pragma unroll
            for (int k = 0; k < 4; k++) acc[i][j][k] = 0.f;

    auto load_stage = [&](uint32_t soff, int kt) {
        uint32_t kb = (uint32_t)kt * 64u;
#pragma unroll
        for (int j = 0; j < 4; j++) {
            cp16(dA[j] + soff, Ab + aoff[j] + kb);
            cp16(dB[j] + soff, Bb + boff[j] + kb);
        }
        CP_COMMIT();
    };

    auto compute_stage = [&](uint32_t soff) {
#pragma unroll
        for (int s = 0; s < 2; s++) {
            uint32_t bh[2][4], bl[2][4];
#pragma unroll
            for (int p = 0; p < 2; p++) {
                uint32_t pb = PB[p] + soff;
                ldm4(pb ^ (uint32_t)(s * 32), bh[p][0], bh[p][1], bh[p][2], bh[p][3]);
                ldm4(pb ^ (uint32_t)(s * 32 + 64), bl[p][0], bl[p][1], bl[p][2], bl[p][3]);
            }
#pragma unroll
            for (int mf = 0; mf < 4; mf++) {
                uint32_t pa = PA[mf] + soff;
                uint32_t ah[4], al[4];
                ldm4(pa ^ (uint32_t)(s * 32), ah[0], ah[1], ah[2], ah[3]);
                ldm4(pa ^ (uint32_t)(s * 32 + 64), al[0], al[1], al[2], al[3]);
#pragma unroll
                for (int nf = 0; nf < 4; nf++) {
                    const int p = nf >> 1, q = nf & 1;
                    mma_bf16(acc[mf][nf], ah, bh[p][q], bh[p][q + 2]);
                }
#pragma unroll
                for (int nf = 0; nf < 4; nf++) {
                    const int p = nf >> 1, q = nf & 1;
                    mma_bf16(acc[mf][nf], ah, bl[p][q], bl[p][q + 2]);
                }
#pragma unroll
                for (int nf = 0; nf < 4; nf++) {
                    const int p = nf >> 1, q = nf & 1;
                    mma_bf16(acc[mf][nf], al, bh[p][q], bh[p][q + 2]);
                }
            }
        }
    };

    load_stage(0u, 0);
    load_stage(STAGE_SZ, 1);

#pragma unroll 1
    for (int kt = 0; kt < KT32 - 1; kt += 3) {
        CP_WAIT1(); __syncthreads();
        if (kt + 2 < KT32) load_stage(2u * STAGE_SZ, kt + 2);
        compute_stage(0u);
        CP_WAIT1(); __syncthreads();
        if (kt + 3 < KT32) load_stage(0u, kt + 3);
        compute_stage(STAGE_SZ);
        CP_WAIT1(); __syncthreads();
        if (kt + 4 < KT32) load_stage(STAGE_SZ, kt + 4);
        compute_stage(2u * STAGE_SZ);
    }
    CP_WAIT0(); __syncthreads();
    compute_stage(0u);     // kt = 63, slot 0

    // ---- epilogue: coef-scaled write into per-slot buffer -------------------
    const int qr = lane >> 2, qc = (lane & 3) * 2;
#pragma unroll
    for (int mf = 0; mf < 4; mf++) {
#pragma unroll
        for (int rr = 0; rr < 2; rr++) {
            int r = warp_m * 64 + mf * 16 + qr + rr * 8;
            if (m0 + r < cnt) {
                int gi = base + m0 + r;
                int token = g_tok[gi];
                float coef = g_cf[gi];
                float* yrow = g_y[g_slot[gi]] + (size_t)token * H_DIM + n0;
#pragma unroll
                for (int nf = 0; nf < 4; nf++) {
                    int c = warp_n * 32 + nf * 8 + qc;
                    float2 v;
                    v.x = coef * acc[mf][nf][rr * 2];
                    v.y = coef * acc[mf][nf][rr * 2 + 1];
                    *(float2*)(yrow + c) = v;
                }
            }
        }
    }
}

// ---------------- launch ----------------------------------------------------
extern "C" void kernel_launch(void* const* d_in, const int* in_sizes, int n_in,
                              void* d_out, int out_size) {
    const float* x = (const float*)d_in[0];
    const float* gw = (const float*)d_in[1];
    const float* ws = (const float*)d_in[2];
    const float* w2s = (const float*)d_in[3];
    float* out = (float*)d_out;

    cudaFuncSetAttribute(gemm1_mma, cudaFuncAttributeMaxDynamicSharedMemorySize, SMEM_DYN);
    cudaFuncSetAttribute(gemm2_mma, cudaFuncAttributeMaxDynamicSharedMemorySize, SMEM_DYN);

    // gemm1_mma stays the 4th launch (ncu capture slot)
    gate_kernel<<<T_TOK / 16, 256>>>(x, gw);
    cvt_all<<<4096, 256>>>(x, ws, w2s);
    scan_scatter<<<1, 256>>>();

    dim3 grid1(I_DIM / 64, MAXTILE);
    gemm1_mma<<<grid1, 256, SMEM_DYN>>>();

    dim3 grid2(H_DIM / 128, MAXTILE);
    gemm2_mma<<<grid2, 256, SMEM_DYN>>>();

    combine_kernel<<<2048, 256>>>(out);
}

// round 17
// speedup vs baseline: 1.0938x; 1.0938x over previous
#include <cuda_runtime.h>
#include <cuda_bf16.h>
#include <cstdint>
#include <cstddef>
#include <math.h>

#define T_TOK 4096
#define H_DIM 2048
#define I_DIM 2048
#define N_EXP 16
#define TOPK  2
#define NROWS (T_TOK * TOPK)
#define HPAD  128
#define MAXTILE 80

#define BK32   32
#define KT32   (H_DIM / BK32)     // 64
#define TILE_SZ 16384u            // 128 rows x 128B (hi|lo interleaved)
#define STAGE_SZ 32768u           // A tile + B tile
#define SMEM_DYN (3 * STAGE_SZ + 128)

// ---------------- routing scratch -------------------------------------------
__device__ int   g_offset[N_EXP + 1];
__device__ int   g_tids[NROWS];
__device__ float g_tw[NROWS];
__device__ int   g_tok[NROWS + HPAD];
__device__ float g_cf[NROWS + HPAD];
__device__ int   g_slot[NROWS + HPAD];
__device__ int   g_tile_e[MAXTILE];
__device__ int   g_tile_m0[MAXTILE];
__device__ int   g_ntile;

// ---------------- bf16 hi/lo split operand storage --------------------------
__device__ __nv_bfloat16 xb_hi[(size_t)T_TOK * H_DIM];
__device__ __nv_bfloat16 xb_lo[(size_t)T_TOK * H_DIM];
__device__ __nv_bfloat16 wsb_hi[(size_t)N_EXP * 2 * I_DIM * H_DIM];
__device__ __nv_bfloat16 wsb_lo[(size_t)N_EXP * 2 * I_DIM * H_DIM];
__device__ __nv_bfloat16 w2b_hi[(size_t)N_EXP * H_DIM * I_DIM];
__device__ __nv_bfloat16 w2b_lo[(size_t)N_EXP * H_DIM * I_DIM];
__device__ __nv_bfloat16 hb_hi[(size_t)(NROWS + HPAD) * I_DIM];
__device__ __nv_bfloat16 hb_lo[(size_t)(NROWS + HPAD) * I_DIM];
__device__ float g_y[TOPK][(size_t)T_TOK * H_DIM];

// ---------------- helpers ----------------------------------------------------
__device__ __forceinline__ uint32_t smem_u32(const void* p) {
    uint32_t r;
    asm("{ .reg .u64 t; cvta.to.shared.u64 t, %1; cvt.u32.u64 %0, t; }"
        : "=r"(r) : "l"(p));
    return r;
}
__device__ __forceinline__ void ldm4(uint32_t a, uint32_t& r0, uint32_t& r1,
                                     uint32_t& r2, uint32_t& r3) {
    asm volatile("ldmatrix.sync.aligned.m8n8.x4.shared.b16 {%0,%1,%2,%3}, [%4];"
                 : "=r"(r0), "=r"(r1), "=r"(r2), "=r"(r3) : "r"(a));
}
__device__ __forceinline__ void mma_bf16(float* d, const uint32_t* a,
                                         uint32_t b0, uint32_t b1) {
    asm volatile(
        "mma.sync.aligned.m16n8k16.row.col.f32.bf16.bf16.f32 "
        "{%0,%1,%2,%3}, {%4,%5,%6,%7}, {%8,%9}, {%0,%1,%2,%3};"
        : "+f"(d[0]), "+f"(d[1]), "+f"(d[2]), "+f"(d[3])
        : "r"(a[0]), "r"(a[1]), "r"(a[2]), "r"(a[3]), "r"(b0), "r"(b1));
}
__device__ __forceinline__ uint32_t pack_bf16(__nv_bfloat16 a, __nv_bfloat16 b) {
    return (uint32_t)__bfloat16_as_ushort(a) |
           ((uint32_t)__bfloat16_as_ushort(b) << 16);
}
__device__ __forceinline__ void cp16(uint32_t dst, const void* src) {
    asm volatile("cp.async.cg.shared.global [%0], [%1], 16;" :: "r"(dst), "l"(src) : "memory");
}
#define CP_COMMIT() asm volatile("cp.async.commit_group;" ::: "memory")
#define CP_WAIT1()  asm volatile("cp.async.wait_group 1;" ::: "memory")
#define CP_WAIT0()  asm volatile("cp.async.wait_group 0;" ::: "memory")

// swizzled in-tile byte offset for (row, chunk16B) — cp.async store path
__device__ __forceinline__ uint32_t tof(int row, int ch) {
    return (uint32_t)(row * 128 + ((ch ^ (row & 7)) * 16));
}

// ---------------- gating: tiled 16 tokens x 16 experts -----------------------
__global__ __launch_bounds__(256) void gate_kernel(const float* __restrict__ x,
                                                   const float* __restrict__ gw) {
    __shared__ __align__(16) float xs[16][132];
    __shared__ __align__(16) float gs[16][132];
    __shared__ float lg[16][17];

    int tid = threadIdx.x;
    int t0  = blockIdx.x * 16;
    int tok = tid >> 4;
    int e   = tid & 15;
    float acc = 0.f;

    for (int kc = 0; kc < H_DIM; kc += 128) {
        __syncthreads();
        for (int i = tid; i < 512; i += 256) {
            int r = i >> 5, c4 = i & 31;
            *(float4*)&xs[r][c4 * 4] =
                *(const float4*)(x + (size_t)(t0 + r) * H_DIM + kc + c4 * 4);
            *(float4*)&gs[r][c4 * 4] =
                *(const float4*)(gw + (size_t)r * H_DIM + kc + c4 * 4);
        }
        __syncthreads();
#pragma unroll 16
        for (int k = 0; k < 128; k++) acc += xs[tok][k] * gs[e][k];
    }
    lg[tok][e] = acc;
    __syncthreads();

    if (tid < 16) {
        int t = t0 + tid;
        int b0 = 0; float v0 = lg[tid][0];
        for (int j = 1; j < N_EXP; j++)
            if (lg[tid][j] > v0) { v0 = lg[tid][j]; b0 = j; }
        int b1 = -1; float v1 = -3.4e38f;
        for (int j = 0; j < N_EXP; j++) {
            if (j == b0) continue;
            if (lg[tid][j] > v1) { v1 = lg[tid][j]; b1 = j; }
        }
        float w0 = 1.0f / (1.0f + expf(v1 - v0));
        g_tids[2 * t] = b0;   g_tids[2 * t + 1] = b1;
        g_tw[2 * t] = w0;     g_tw[2 * t + 1] = 1.0f - w0;
    }
}

// ---------------- fused fp32 -> bf16 hi/lo split of x, ws, w2s ---------------
__global__ __launch_bounds__(256) void cvt_all(const float* __restrict__ x,
                                               const float* __restrict__ ws,
                                               const float* __restrict__ w2s) {
    const size_t X4  = (size_t)T_TOK * H_DIM / 4;
    const size_t WS4 = (size_t)N_EXP * 2 * I_DIM * H_DIM / 4;
    const size_t W24 = (size_t)N_EXP * H_DIM * I_DIM / 4;
    const size_t TOT = X4 + WS4 + W24;
    size_t i = (size_t)blockIdx.x * blockDim.x + threadIdx.x;
    size_t stride = (size_t)gridDim.x * blockDim.x;
    for (; i < TOT; i += stride) {
        const float4* s4;
        uint2 *h2, *l2;
        size_t j;
        if (i < X4) {
            j = i; s4 = (const float4*)x;
            h2 = (uint2*)xb_hi; l2 = (uint2*)xb_lo;
        } else if (i < X4 + WS4) {
            j = i - X4; s4 = (const float4*)ws;
            h2 = (uint2*)wsb_hi; l2 = (uint2*)wsb_lo;
        } else {
            j = i - X4 - WS4; s4 = (const float4*)w2s;
            h2 = (uint2*)w2b_hi; l2 = (uint2*)w2b_lo;
        }
        float4 v = s4[j];
        __nv_bfloat16 h0 = __float2bfloat16_rn(v.x), h1 = __float2bfloat16_rn(v.y);
        __nv_bfloat16 hb = __float2bfloat16_rn(v.z), h3 = __float2bfloat16_rn(v.w);
        float l0 = v.x - __bfloat162float(h0), l1 = v.y - __bfloat162float(h1);
        float l2f = v.z - __bfloat162float(hb), l3 = v.w - __bfloat162float(h3);
        uint2 ph; ph.x = pack_bf16(h0, h1); ph.y = pack_bf16(hb, h3);
        uint2 pl;
        pl.x = pack_bf16(__float2bfloat16_rn(l0), __float2bfloat16_rn(l1));
        pl.y = pack_bf16(__float2bfloat16_rn(l2f), __float2bfloat16_rn(l3));
        h2[j] = ph;
        l2[j] = pl;
    }
}

// ---------------- single-block: count + prefix + scatter + tile list ---------
__global__ __launch_bounds__(256) void scan_scatter() {
    __shared__ int scnt[N_EXP];
    __shared__ int scur[N_EXP];
    __shared__ int soff[N_EXP];
    int tid = threadIdx.x;
    if (tid < N_EXP) { scnt[tid] = 0; scur[tid] = 0; }
    __syncthreads();
    for (int i = tid; i < NROWS; i += 256) atomicAdd(&scnt[g_tids[i]], 1);
    __syncthreads();
    if (tid == 0) {
        int s = 0, nt = 0;
        for (int e = 0; e < N_EXP; e++) {
            soff[e] = s; g_offset[e] = s;
            for (int m0 = 0; m0 < scnt[e]; m0 += 128) {
                g_tile_e[nt] = e; g_tile_m0[nt] = m0; nt++;
            }
            s += scnt[e];
        }
        g_offset[N_EXP] = s;
        g_ntile = nt;
    }
    __syncthreads();
    for (int t = tid; t < T_TOK; t += 256) {
#pragma unroll
        for (int k = 0; k < TOPK; k++) {
            int e = g_tids[2 * t + k];
            int pos = atomicAdd(&scur[e], 1);
            int r = soff[e] + pos;
            g_tok[r] = t; g_cf[r] = g_tw[2 * t + k]; g_slot[r] = k;
        }
    }
}

__global__ void combine_kernel(float* __restrict__ out) {
    size_t i = (size_t)blockIdx.x * blockDim.x + threadIdx.x;
    size_t n = (size_t)T_TOK * H_DIM / 4;
    size_t stride = (size_t)gridDim.x * blockDim.x;
    const float4* y0 = (const float4*)g_y[0];
    const float4* y1 = (const float4*)g_y[1];
    float4* o = (float4*)out;
    for (; i < n; i += stride) {
        float4 a = y0[i], b = y1[i];
        o[i] = make_float4(a.x + b.x, a.y + b.y, a.z + b.z, a.w + b.w);
    }
}

// ---------------- GEMM1: h = silu(x@Wg^T)*(x@Wu^T) ---------------------------
__global__ __launch_bounds__(256, 2) void gemm1_mma() {
    const int ts = blockIdx.y;
    if (ts >= g_ntile) return;
    const int e    = g_tile_e[ts];
    const int m0   = g_tile_m0[ts];
    const int base = g_offset[e];
    const int cnt  = g_offset[e + 1] - base;
    const int n0g  = blockIdx.x * 64;

    extern __shared__ __align__(128) char smem[];
    __shared__ int s_tok[128];
    const uint32_t sb = (smem_u32(smem) + 127u) & ~127u;

    const int tid = threadIdx.x;
    const int wid = tid >> 5, lane = tid & 31;
    const int warp_m = wid >> 2, warp_n = wid & 3;

    if (tid < 128) s_tok[tid] = (m0 + tid < cnt) ? g_tok[base + m0 + tid] : g_tok[base];
    __syncthreads();

    // ---- loader geometry: 4 rows/tile/thread, fixed 16B chunk --------------
    const int rbase = tid >> 3;          // 0..31
    const int ch    = tid & 7;           // <4 hi, >=4 lo
    const int kch   = ch & 3;
    const bool isLo = ch >= 4;
    const char* Ab = (const char*)(isLo ? xb_lo : xb_hi);
    const char* Bb = (const char*)(isLo ? wsb_lo : wsb_hi);
    uint32_t aoff[4];
#pragma unroll
    for (int j = 0; j < 4; j++)
        aoff[j] = ((uint32_t)s_tok[rbase + j * 32] * H_DIM + kch * 8) * 2u;
    // B rows: j=0,1 -> gate rows n0g+rbase+32j ; j=2,3 -> up rows
    const uint32_t boff_g = ((uint32_t)(e * 2 * I_DIM + n0g + rbase) * H_DIM + kch * 8) * 2u;
    const uint32_t boff_u = ((uint32_t)(e * 2 * I_DIM + I_DIM + n0g + rbase) * H_DIM + kch * 8) * 2u;
    const uint32_t dA0 = sb + tof(rbase, ch);           // +j*4096 per row group
    const uint32_t dB0 = sb + TILE_SZ + tof(rbase, ch);

    // ---- ldsm address bases (XOR-folded swizzle) ---------------------------
    const int lrow = lane & 15;
    const uint32_t X = (uint32_t)(lane >> 4) * 16u;
    uint32_t PB[2], PA[4];
#pragma unroll
    for (int p = 0; p < 2; p++) {
        int r = warp_n * 32 + p * 16 + lrow;
        PB[p] = (sb + TILE_SZ + (uint32_t)r * 128u + (uint32_t)(r & 7) * 16u) ^ X;
    }
#pragma unroll
    for (int mf = 0; mf < 4; mf++) {
        int r = warp_m * 64 + mf * 16 + lrow;
        PA[mf] = (sb + (uint32_t)r * 128u + (uint32_t)(r & 7) * 16u) ^ X;
    }

    float acc[4][4][4];
#pragma unroll
    for (int i = 0; i < 4; i++)
#pragma unroll
        for (int j = 0; j < 4; j++)
#pragma unroll
            for (int k = 0; k < 4; k++) acc[i][j][k] = 0.f;

    auto load_stage = [&](uint32_t so, int kt) {
        uint32_t kb = (uint32_t)kt * 64u;
#pragma unroll
        for (int j = 0; j < 4; j++) {
            cp16(dA0 + so + (uint32_t)j * 4096u, Ab + aoff[j] + kb);
            uint32_t bo = (j < 2) ? (boff_g + (uint32_t)j * 131072u)
                                  : (boff_u + (uint32_t)(j - 2) * 131072u);
            cp16(dB0 + so + (uint32_t)j * 4096u, Bb + bo + kb);
        }
        CP_COMMIT();
    };

    auto compute_stage = [&](uint32_t so) {
#pragma unroll
        for (int s = 0; s < 2; s++) {
            const uint32_t xs0 = (uint32_t)(s * 32), xs1 = (uint32_t)(s * 32 + 64);
            uint32_t bh[2][4], bl[2][4];
#pragma unroll
            for (int p = 0; p < 2; p++) {
                uint32_t pb = PB[p] + so;
                ldm4(pb ^ xs0, bh[p][0], bh[p][1], bh[p][2], bh[p][3]);
                ldm4(pb ^ xs1, bl[p][0], bl[p][1], bl[p][2], bl[p][3]);
            }
            uint32_t ah[2][4], al[2][4];
            {   // preload mf=0 A fragments
                uint32_t pa = PA[0] + so;
                ldm4(pa ^ xs0, ah[0][0], ah[0][1], ah[0][2], ah[0][3]);
                ldm4(pa ^ xs1, al[0][0], al[0][1], al[0][2], al[0][3]);
            }
#pragma unroll
            for (int mf = 0; mf < 4; mf++) {
                const int cur = mf & 1, nxt = cur ^ 1;
                if (mf + 1 < 4) {   // prefetch next mf's A while mma runs
                    uint32_t pa = PA[mf + 1] + so;
                    ldm4(pa ^ xs0, ah[nxt][0], ah[nxt][1], ah[nxt][2], ah[nxt][3]);
                    ldm4(pa ^ xs1, al[nxt][0], al[nxt][1], al[nxt][2], al[nxt][3]);
                }
#pragma unroll
                for (int nf = 0; nf < 4; nf++) {
                    const int p = nf >> 1, q = nf & 1;
                    mma_bf16(acc[mf][nf], ah[cur], bh[p][q], bh[p][q + 2]);
                }
#pragma unroll
                for (int nf = 0; nf < 4; nf++) {
                    const int p = nf >> 1, q = nf & 1;
                    mma_bf16(acc[mf][nf], ah[cur], bl[p][q], bl[p][q + 2]);
                }
#pragma unroll
                for (int nf = 0; nf < 4; nf++) {
                    const int p = nf >> 1, q = nf & 1;
                    mma_bf16(acc[mf][nf], al[cur], bh[p][q], bh[p][q + 2]);
                }
            }
        }
    };

    load_stage(0u, 0);
    load_stage(STAGE_SZ, 1);

    uint32_t sA = 0u, sB = STAGE_SZ, sC = 2u * STAGE_SZ;
#pragma unroll 1
    for (int kt = 0; kt < KT32; kt++) {
        if (kt + 1 < KT32) CP_WAIT1(); else CP_WAIT0();
        __syncthreads();
        if (kt + 2 < KT32) load_stage(sC, kt + 2);
        compute_stage(sA);
        uint32_t t = sA; sA = sB; sB = sC; sC = t;
    }

    // ---- epilogue: exchange gate via smem, fused SiLU, write bf16 h --------
    __syncthreads();
    float* sg = (float*)smem;            // [128][68]
    const int qr = lane >> 2, qc = (lane & 3) * 2;
    if (warp_n < 2) {
#pragma unroll
        for (int mf = 0; mf < 4; mf++)
#pragma unroll
            for (int nf = 0; nf < 4; nf++) {
                int r = warp_m * 64 + mf * 16 + qr;
                int c = warp_n * 32 + nf * 8 + qc;
                sg[r * 68 + c]           = acc[mf][nf][0];
                sg[r * 68 + c + 1]       = acc[mf][nf][1];
                sg[(r + 8) * 68 + c]     = acc[mf][nf][2];
                sg[(r + 8) * 68 + c + 1] = acc[mf][nf][3];
            }
    }
    __syncthreads();
    if (warp_n >= 2) {
#pragma unroll
        for (int mf = 0; mf < 4; mf++)
#pragma unroll
            for (int nf = 0; nf < 4; nf++) {
                int r = warp_m * 64 + mf * 16 + qr;
                int cu = (warp_n - 2) * 32 + nf * 8 + qc;
#pragma unroll
                for (int rr = 0; rr < 2; rr++) {
                    int rloc = r + rr * 8;
                    if (m0 + rloc < cnt) {
                        float g0 = sg[rloc * 68 + cu];
                        float g1 = sg[rloc * 68 + cu + 1];
                        float u0 = acc[mf][nf][rr * 2];
                        float u1 = acc[mf][nf][rr * 2 + 1];
                        float h0 = g0 / (1.0f + expf(-g0)) * u0;
                        float h1 = g1 / (1.0f + expf(-g1)) * u1;
                        size_t idx = (size_t)(base + m0 + rloc) * I_DIM + n0g + cu;
                        __nv_bfloat16 b0 = __float2bfloat16_rn(h0);
                        __nv_bfloat16 b1 = __float2bfloat16_rn(h1);
                        float l0 = h0 - __bfloat162float(b0);
                        float l1 = h1 - __bfloat162float(b1);
                        *(uint32_t*)(hb_hi + idx) = pack_bf16(b0, b1);
                        *(uint32_t*)(hb_lo + idx) =
                            pack_bf16(__float2bfloat16_rn(l0), __float2bfloat16_rn(l1));
                    }
                }
            }
    }
}

// ---------------- GEMM2: y[slot] = coef * (h @ W2^T) -------------------------
__global__ __launch_bounds__(256, 2) void gemm2_mma() {
    const int ts = blockIdx.y;
    if (ts >= g_ntile) return;
    const int e    = g_tile_e[ts];
    const int m0   = g_tile_m0[ts];
    const int base = g_offset[e];
    const int cnt  = g_offset[e + 1] - base;
    const int n0   = blockIdx.x * 128;

    extern __shared__ __align__(128) char smem[];
    const uint32_t sb = (smem_u32(smem) + 127u) & ~127u;

    const int tid = threadIdx.x;
    const int wid = tid >> 5, lane = tid & 31;
    const int warp_m = wid >> 2, warp_n = wid & 3;

    const int rbase = tid >> 3;
    const int ch    = tid & 7;
    const int kch   = ch & 3;
    const bool isLo = ch >= 4;
    const char* Ab = (const char*)(isLo ? hb_lo : hb_hi);
    const char* Bb = (const char*)(isLo ? w2b_lo : w2b_hi);
    uint32_t aoff[4];
#pragma unroll
    for (int j = 0; j < 4; j++) {
        int row = rbase + j * 32;
        int ridx = (m0 + row < cnt) ? (base + m0 + row) : base;
        aoff[j] = ((uint32_t)ridx * I_DIM + kch * 8) * 2u;
    }
    const uint32_t boff0 = ((uint32_t)(e * H_DIM + n0 + rbase) * I_DIM + kch * 8) * 2u;
    const uint32_t dA0 = sb + tof(rbase, ch);
    const uint32_t dB0 = sb + TILE_SZ + tof(rbase, ch);

    const int lrow = lane & 15;
    const uint32_t X = (uint32_t)(lane >> 4) * 16u;
    uint32_t PB[2], PA[4];
#pragma unroll
    for (int p = 0; p < 2; p++) {
        int r = warp_n * 32 + p * 16 + lrow;
        PB[p] = (sb + TILE_SZ + (uint32_t)r * 128u + (uint32_t)(r & 7) * 16u) ^ X;
    }
#pragma unroll
    for (int mf = 0; mf < 4; mf++) {
        int r = warp_m * 64 + mf * 16 + lrow;
        PA[mf] = (sb + (uint32_t)r * 128u + (uint32_t)(r & 7) * 16u) ^ X;
    }

    float acc[4][4][4];
#pragma unroll
    for (int i = 0; i < 4; i++)
#pragma unroll
        for (int j = 0; j < 4; j++)
#pragma unroll
            for (int k = 0; k < 4; k++) acc[i][j][k] = 0.f;

    auto load_stage = [&](uint32_t so, int kt) {
        uint32_t kb = (uint32_t)kt * 64u;
#pragma unroll
        for (int j = 0; j < 4; j++) {
            cp16(dA0 + so + (uint32_t)j * 4096u, Ab + aoff[j] + kb);
            cp16(dB0 + so + (uint32_t)j * 4096u, Bb + boff0 + (uint32_t)j * 131072u + kb);
        }
        CP_COMMIT();
    };

    auto compute_stage = [&](uint32_t so) {
#pragma unroll
        for (int s = 0; s < 2; s++) {
            const uint32_t xs0 = (uint32_t)(s * 32), xs1 = (uint32_t)(s * 32 + 64);
            uint32_t bh[2][4], bl[2][4];
#pragma unroll
            for (int p = 0; p < 2; p++) {
                uint32_t pb = PB[p] + so;
                ldm4(pb ^ xs0, bh[p][0], bh[p][1], bh[p][2], bh[p][3]);
                ldm4(pb ^ xs1, bl[p][0], bl[p][1], bl[p][2], bl[p][3]);
            }
            uint32_t ah[2][4], al[2][4];
            {
                uint32_t pa = PA[0] + so;
                ldm4(pa ^ xs0, ah[0][0], ah[0][1], ah[0][2], ah[0][3]);
                ldm4(pa ^ xs1, al[0][0], al[0][1], al[0][2], al[0][3]);
            }
#pragma unroll
            for (int mf = 0; mf < 4; mf++) {
                const int cur = mf & 1, nxt = cur ^ 1;
                if (mf + 1 < 4) {
                    uint32_t pa = PA[mf + 1] + so;
                    ldm4(pa ^ xs0, ah[nxt][0], ah[nxt][1], ah[nxt][2], ah[nxt][3]);
                    ldm4(pa ^ xs1, al[nxt][0], al[nxt][1], al[nxt][2], al[nxt][3]);
                }
#pragma unroll
                for (int nf = 0; nf < 4; nf++) {
                    const int p = nf >> 1, q = nf & 1;
                    mma_bf16(acc[mf][nf], ah[cur], bh[p][q], bh[p][q + 2]);
                }
#pragma unroll
                for (int nf = 0; nf < 4; nf++) {
                    const int p = nf >> 1, q = nf & 1;
                    mma_bf16(acc[mf][nf], ah[cur], bl[p][q], bl[p][q + 2]);
                }
#pragma unroll
                for (int nf = 0; nf < 4; nf++) {
                    const int p = nf >> 1, q = nf & 1;
                    mma_bf16(acc[mf][nf], al[cur], bh[p][q], bh[p][q + 2]);
                }
            }
        }
    };

    load_stage(0u, 0);
    load_stage(STAGE_SZ, 1);

    uint32_t sA = 0u, sB = STAGE_SZ, sC = 2u * STAGE_SZ;
#pragma unroll 1
    for (int kt = 0; kt < KT32; kt++) {
        if (kt + 1 < KT32) CP_WAIT1(); else CP_WAIT0();
        __syncthreads();
        if (kt + 2 < KT32) load_stage(sC, kt + 2);
        compute_stage(sA);
        uint32_t t = sA; sA = sB; sB = sC; sC = t;
    }

    // ---- epilogue: coef-scaled write into per-slot buffer -------------------
    const int qr = lane >> 2, qc = (lane & 3) * 2;
#pragma unroll
    for (int mf = 0; mf < 4; mf++) {
#pragma unroll
        for (int rr = 0; rr < 2; rr++) {
            int r = warp_m * 64 + mf * 16 + qr + rr * 8;
            if (m0 + r < cnt) {
                int gi = base + m0 + r;
                int token = g_tok[gi];
                float coef = g_cf[gi];
                float* yrow = g_y[g_slot[gi]] + (size_t)token * H_DIM + n0;
#pragma unroll
                for (int nf = 0; nf < 4; nf++) {
                    int c = warp_n * 32 + nf * 8 + qc;
                    float2 v;
                    v.x = coef * acc[mf][nf][rr * 2];
                    v.y = coef * acc[mf][nf][rr * 2 + 1];
                    *(float2*)(yrow + c) = v;
                }
            }
        }
    }
}

// ---------------- launch ----------------------------------------------------
extern "C" void kernel_launch(void* const* d_in, const int* in_sizes, int n_in,
                              void* d_out, int out_size) {
    const float* x = (const float*)d_in[0];
    const float* gw = (const float*)d_in[1];
    const float* ws = (const float*)d_in[2];
    const float* w2s = (const float*)d_in[3];
    float* out = (float*)d_out;

    cudaFuncSetAttribute(gemm1_mma, cudaFuncAttributeMaxDynamicSharedMemorySize, SMEM_DYN);
    cudaFuncSetAttribute(gemm2_mma, cudaFuncAttributeMaxDynamicSharedMemorySize, SMEM_DYN);

    // gemm1_mma stays the 4th launch (ncu capture slot)
    gate_kernel<<<T_TOK / 16, 256>>>(x, gw);
    cvt_all<<<4096, 256>>>(x, ws, w2s);
    scan_scatter<<<1, 256>>>();

    dim3 grid1(I_DIM / 64, MAXTILE);
    gemm1_mma<<<grid1, 256, SMEM_DYN>>>();

    dim3 grid2(H_DIM / 128, MAXTILE);
    gemm2_mma<<<grid2, 256, SMEM_DYN>>>();

    combine_kernel<<<2048, 256>>>(out);
}